// round 16
// baseline (speedup 1.0000x reference)
#include <cuda_runtime.h>
#include <cuda_fp16.h>
#include <math.h>
#include <stdint.h>

#define FEAT 128
#define OUTF 16
#define NMAX 50000
#define EMAX 800000
#define BN_EPS 1e-5f
#define EBLK 256            // grid-stride worker blocks
#define XPAD 136            // smem row pitch in halves (conflict-free frag loads)

typedef unsigned long long u64;

// ---------------- scratch (no allocations allowed) ----------------
__device__ __half g_hh[(size_t)NMAX * FEAT];   // fp16 GEMM output (layers 1-2)
__device__ __half g_x2h[(size_t)NMAX * FEAT];  // fp16 post-aggregation activation
__device__ float  g_h16[(size_t)NMAX * OUTF];  // fp32 GEMM output (layer 3)
__device__ unsigned g_w1p[8192];               // W1 fragment-permuted fp16x2
__device__ unsigned g_w2p[8192];               // W2 fragment-permuted fp16x2
__device__ int    g_deg[NMAX];                 // zero at module load; re-zeroed by agg16
__device__ int    g_rowptr[NMAX + 1];
__device__ int    g_cursor[NMAX];
__device__ float  g_dinv[NMAX];
__device__ int2   g_csr_sn[EMAX];              // packed (src, norm as dup half2)
__device__ float  g_S[2 * FEAT];
__device__ float  g_T[2 * FEAT];

// ---------------- helpers ----------------
__device__ __forceinline__ unsigned h2bits(__half2 h) {
    return *reinterpret_cast<unsigned*>(&h);
}
__device__ __forceinline__ __half2 bits2h2(unsigned u) {
    return *reinterpret_cast<__half2*>(&u);
}
__device__ __forceinline__ void mma16816(float c[4], const unsigned a[4], const unsigned b[2]) {
    asm volatile(
        "mma.sync.aligned.m16n8k16.row.col.f32.f16.f16.f32 "
        "{%0,%1,%2,%3}, {%4,%5,%6,%7}, {%8,%9}, {%0,%1,%2,%3};"
        : "+f"(c[0]), "+f"(c[1]), "+f"(c[2]), "+f"(c[3])
        : "r"(a[0]), "r"(a[1]), "r"(a[2]), "r"(a[3]), "r"(b[0]), "r"(b[1]));
}

// ---------------- HMMA GEMM block: X tile in smem, W fragment-permuted in global ----------------
// Xv is fp32 (xhalf=false) or fp16 (xhalf=true); converted to fp16 during staging.
__device__ __forceinline__ void gemm128_block(const void* Xv, bool xhalf,
                                              const unsigned* __restrict__ Wp,
                                              __half* __restrict__ C,
                                              int n, int row0) {
    __shared__ __align__(16) __half xs[64 * XPAD];
    int t = threadIdx.x;

    // stage X tile (coalesced; rows >= n zero-filled)
    {
        int r  = t >> 2;
        int cg = t & 3;
        int grow = row0 + r;
        bool ok = grow < n;
        if (xhalf) {
            const uint2* src = (const uint2*)((const __half*)Xv + (size_t)grow * FEAT + cg * 32);
#pragma unroll
            for (int u = 0; u < 8; u++) {
                uint2 v = ok ? __ldg(src + u) : make_uint2(0u, 0u);
                *(uint2*)(xs + r * XPAD + cg * 32 + u * 4) = v;
            }
        } else {
            const float4* src = (const float4*)((const float*)Xv + (size_t)grow * FEAT + cg * 32);
#pragma unroll
            for (int u = 0; u < 8; u++) {
                float4 v = ok ? __ldg(src + u) : make_float4(0.f, 0.f, 0.f, 0.f);
                uint2 p = make_uint2(h2bits(__floats2half2_rn(v.x, v.y)),
                                     h2bits(__floats2half2_rn(v.z, v.w)));
                *(uint2*)(xs + r * XPAD + cg * 32 + u * 4) = p;
            }
        }
    }
    __syncthreads();

    int lane = t & 31, w = t >> 5;
    int wm = w >> 2, wn = w & 3;          // m-half (32 rows), n-quarter (32 cols)
    int grp = lane >> 2, qid = lane & 3;
    int k2 = qid * 2;

    float acc[2][4][4];
#pragma unroll
    for (int mt = 0; mt < 2; mt++)
#pragma unroll
        for (int nt = 0; nt < 4; nt++)
#pragma unroll
            for (int f = 0; f < 4; f++) acc[mt][nt][f] = 0.f;

#pragma unroll
    for (int ks = 0; ks < 8; ks++) {
        int k0 = ks * 16;
        unsigned a[2][4];
#pragma unroll
        for (int mt = 0; mt < 2; mt++) {
            const __half* base = xs + (wm * 32 + mt * 16 + grp) * XPAD + k0 + k2;
            a[mt][0] = *(const unsigned*)(base);
            a[mt][1] = *(const unsigned*)(base + 8 * XPAD);
            a[mt][2] = *(const unsigned*)(base + 8);
            a[mt][3] = *(const unsigned*)(base + 8 * XPAD + 8);
        }
        unsigned b[4][2];
#pragma unroll
        for (int nt = 0; nt < 4; nt++) {
            const unsigned* wp = Wp + ((((wn * 4 + nt) * 8 + ks) * 2) * 32) + lane;
            b[nt][0] = __ldg(wp);
            b[nt][1] = __ldg(wp + 32);
        }
#pragma unroll
        for (int nt = 0; nt < 4; nt++) {
            mma16816(acc[0][nt], a[0], b[nt]);
            mma16816(acc[1][nt], a[1], b[nt]);
        }
    }

#pragma unroll
    for (int mt = 0; mt < 2; mt++) {
        int r0 = row0 + wm * 32 + mt * 16 + grp;
        int r1 = r0 + 8;
#pragma unroll
        for (int nt = 0; nt < 4; nt++) {
            int cc = wn * 32 + nt * 8 + qid * 2;
            if (r0 < n)
                *(unsigned*)(C + (size_t)r0 * FEAT + cc) =
                    h2bits(__floats2half2_rn(acc[mt][nt][0], acc[mt][nt][1]));
            if (r1 < n)
                *(unsigned*)(C + (size_t)r1 * FEAT + cc) =
                    h2bits(__floats2half2_rn(acc[mt][nt][2], acc[mt][nt][3]));
        }
    }
}

// ---------------- 256-thread scan block: 4 elems/thread, 1024 elems/block ----------------
__device__ __forceinline__ void scan_block_256(int n, int nb, int sbid) {
    __shared__ int ws[8];     // per-warp inclusive sums
    __shared__ int bsum[8];   // per-warp partial of global prefix
    int t = threadIdx.x;
    int lane = t & 31, wid = t >> 5;
    int i0 = sbid * 1024 + t * 4;

    int d0 = (i0     < n) ? g_deg[i0]     : 0;
    int d1 = (i0 + 1 < n) ? g_deg[i0 + 1] : 0;
    int d2 = (i0 + 2 < n) ? g_deg[i0 + 2] : 0;
    int d3 = (i0 + 3 < n) ? g_deg[i0 + 3] : 0;
    if (i0     < n) g_dinv[i0]     = rsqrtf((float)(d0 + 1));  // +1 self loop
    if (i0 + 1 < n) g_dinv[i0 + 1] = rsqrtf((float)(d1 + 1));
    if (i0 + 2 < n) g_dinv[i0 + 2] = rsqrtf((float)(d2 + 1));
    if (i0 + 3 < n) g_dinv[i0 + 3] = rsqrtf((float)(d3 + 1));
    int s = d0 + d1 + d2 + d3;

    // warp inclusive scan of per-thread sums
    int v = s;
#pragma unroll
    for (int o = 1; o < 32; o <<= 1) {
        int u = __shfl_up_sync(0xffffffffu, v, o);
        if (lane >= o) v += u;
    }
    if (lane == 31) ws[wid] = v;

    // global prefix: sum of g_deg[0, sbid*1024)
    int base = sbid * 1024;
    int part = 0;
    for (int j = t; j < base; j += 256) part += g_deg[j];
#pragma unroll
    for (int o = 16; o > 0; o >>= 1) part += __shfl_xor_sync(0xffffffffu, part, o);
    if (lane == 0) bsum[wid] = part;
    __syncthreads();

    int pref = 0;
#pragma unroll
    for (int q = 0; q < 8; q++) pref += bsum[q];
    int wofs = 0;
    for (int q = 0; q < wid; q++) wofs += ws[q];
    int incl = v + wofs;              // inclusive within block (through this thread)
    int r = pref + incl - s;          // exclusive start for this thread's 4 elems

    if (i0     < n) { g_rowptr[i0]     = r; g_cursor[i0]     = r; } r += d0;
    if (i0 + 1 < n) { g_rowptr[i0 + 1] = r; g_cursor[i0 + 1] = r; } r += d1;
    if (i0 + 2 < n) { g_rowptr[i0 + 2] = r; g_cursor[i0 + 2] = r; } r += d2;
    if (i0 + 3 < n) { g_rowptr[i0 + 3] = r; g_cursor[i0 + 3] = r; }

    if (sbid == nb - 1 && t == 255) g_rowptr[n] = pref + incl;
}

// ---------------- prep: BN affine + W fragment permute + degree count ----------------
__global__ void k_prepw(const float* __restrict__ W1, const float* __restrict__ W2,
                        const float* __restrict__ b1, const float* __restrict__ g1,
                        const float* __restrict__ be1, const float* __restrict__ m1,
                        const float* __restrict__ v1,
                        const float* __restrict__ b2, const float* __restrict__ g2,
                        const float* __restrict__ be2, const float* __restrict__ m2,
                        const float* __restrict__ v2,
                        const int* __restrict__ ei, int e, int n) {
    int b = blockIdx.x;
    int t = threadIdx.x;
    if (b == 0) {
        if (t < FEAT) {
            float s = rsqrtf(v1[t] + BN_EPS) * g1[t];
            g_S[t] = s;
            g_T[t] = (b1[t] - m1[t]) * s + be1[t];
        } else {
            int c = t - FEAT;
            float s = rsqrtf(v2[c] + BN_EPS) * g2[c];
            g_S[FEAT + c] = s;
            g_T[FEAT + c] = (b2[c] - m2[c]) * s + be2[c];
        }
        return;
    }
    if (b <= 64) {
        const float* W = (b <= 32) ? W1 : W2;
        unsigned* Wp   = (b <= 32) ? g_w1p : g_w2p;
        int idx = ((b <= 32) ? (b - 1) : (b - 33)) * 256 + t;   // 0..8191
        int lane = idx & 31;
        int reg  = (idx >> 5) & 1;
        int ks   = (idx >> 6) & 7;
        int nt   = (idx >> 9) & 3;
        int wn   = (idx >> 11) & 3;
        int nn = wn * 32 + nt * 8 + (lane >> 2);
        int k  = ks * 16 + (lane & 3) * 2 + reg * 8;
        __half2 v = __floats2half2_rn(W[k * FEAT + nn], W[(k + 1) * FEAT + nn]);
        Wp[idx] = h2bits(v);
        return;
    }
    int wb = b - 65;
    for (int i = wb * 256 + t; i < e; i += EBLK * 256) {
        int d = ei[e + i];
        d = min(max(d, 0), n - 1);
        atomicAdd(&g_deg[d], 1);
    }
}

// ---------------- L2 launch: gemm L1 rows [0,gA*64) || scan blocks ----------------
__global__ __launch_bounds__(256)
void k_gemm_scan(const float* __restrict__ x, const unsigned* __restrict__ Wp,
                 __half* __restrict__ C, int n, int gA, int nb) {
    if ((int)blockIdx.x < gA) {
        gemm128_block(x, false, Wp, C, n, blockIdx.x * 64);
        return;
    }
    scan_block_256(n, nb, blockIdx.x - gA);
}

// ---------------- L3/L5 launch: gemm rows [gA*64, ...) || grid-stride CSR fill ----------------
__global__ __launch_bounds__(256)
void k_gemm_fill(const void* __restrict__ Xv, int xhalf,
                 const unsigned* __restrict__ Wp, __half* __restrict__ C,
                 int n, int gA, int gB, const int* __restrict__ ei, int e) {
    if ((int)blockIdx.x < gB) {
        gemm128_block(Xv, xhalf != 0, Wp, C, n, (gA + blockIdx.x) * 64);
        return;
    }
    for (int i = ((int)blockIdx.x - gB) * 256 + threadIdx.x; i < e; i += EBLK * 256) {
        int s = ei[i];
        int d = ei[e + i];
        s = min(max(s, 0), n - 1);
        d = min(max(d, 0), n - 1);
        int p = atomicAdd(&g_cursor[d], 1);
        float w = g_dinv[s] * g_dinv[d];
        g_csr_sn[p] = make_int2(s, (int)h2bits(__floats2half2_rn(w, w)));
    }
}

// ---------------- pull aggregation (R12-proven): warp/node, half2 accum ----------------
__global__ __launch_bounds__(256) void k_agg128(const __half* __restrict__ hh,
                                                __half* __restrict__ outh,
                                                int soff, int n) {
    int gw   = (blockIdx.x * blockDim.x + threadIdx.x) >> 5;
    int lane = threadIdx.x & 31;
    if (gw >= n) return;
    int node = gw;
    int beg = g_rowptr[node];
    int end = g_rowptr[node + 1];
    float dn = g_dinv[node];
    int c4 = lane * 4;

    __half2 hacc0 = __float2half2_rn(0.f);
    __half2 hacc1 = __float2half2_rn(0.f);

#pragma unroll 4
    for (int e = beg; e < end; e++) {
        int2 p  = __ldg(&g_csr_sn[e]);
        __half2 nh = bits2h2((unsigned)p.y);
        uint2 raw = __ldg((const uint2*)(hh + (size_t)p.x * FEAT + c4));
        hacc0 = __hfma2(nh, bits2h2(raw.x), hacc0);
        hacc1 = __hfma2(nh, bits2h2(raw.y), hacc1);
    }

    float4 acc;
    {
        uint2 raw = __ldg((const uint2*)(hh + (size_t)node * FEAT + c4));
        float2 a = __half22float2(bits2h2(raw.x));
        float2 b = __half22float2(bits2h2(raw.y));
        float w0 = dn * dn;
        float2 e0 = __half22float2(hacc0);
        float2 e1 = __half22float2(hacc1);
        acc.x = fmaf(a.x, w0, e0.x);
        acc.y = fmaf(a.y, w0, e0.y);
        acc.z = fmaf(b.x, w0, e1.x);
        acc.w = fmaf(b.y, w0, e1.y);
    }

    float4 sv = *(const float4*)(g_S + soff + c4);
    float4 tv = *(const float4*)(g_T + soff + c4);
    float ox = fmaxf(fmaf(acc.x, sv.x, tv.x), 0.f);
    float oy = fmaxf(fmaf(acc.y, sv.y, tv.y), 0.f);
    float oz = fmaxf(fmaf(acc.z, sv.z, tv.z), 0.f);
    float ow = fmaxf(fmaf(acc.w, sv.w, tv.w), 0.f);
    uint2 o = make_uint2(h2bits(__floats2half2_rn(ox, oy)),
                         h2bits(__floats2half2_rn(oz, ow)));
    *(uint2*)(outh + (size_t)node * FEAT + c4) = o;
}

// ---------------- GEMM: C[n,16] = X[n,128](fp16) @ W3[128,16] (fp32 math) ----------------
__global__ __launch_bounds__(256) void k_gemm16(const __half* __restrict__ Xh,
                                                const float* __restrict__ W,
                                                float* __restrict__ C, int n) {
    __shared__ float xs[64 * 132];
    int t = threadIdx.x;
    int row0 = blockIdx.x * 64;

    for (int i = t; i < 64 * 32; i += 256) {
        int r  = i >> 5;
        int c4 = (i & 31) * 4;
        float4 v = make_float4(0.f, 0.f, 0.f, 0.f);
        if (row0 + r < n) {
            uint2 raw = __ldg((const uint2*)(Xh + (size_t)(row0 + r) * FEAT + c4));
            float2 a = __half22float2(bits2h2(raw.x));
            float2 b = __half22float2(bits2h2(raw.y));
            v = make_float4(a.x, a.y, b.x, b.y);
        }
        *(float4*)(xs + r * 132 + c4) = v;
    }
    __syncthreads();

    int c4  = (t & 3) * 4;
    int row = t >> 2;
    float4 acc = make_float4(0.f, 0.f, 0.f, 0.f);
    const float* xr = xs + row * 132;
#pragma unroll 4
    for (int k = 0; k < FEAT; k++) {
        float4 wv = __ldg((const float4*)(W + k * OUTF + c4));
        float xv  = xr[k];
        acc.x = fmaf(xv, wv.x, acc.x);
        acc.y = fmaf(xv, wv.y, acc.y);
        acc.z = fmaf(xv, wv.z, acc.z);
        acc.w = fmaf(xv, wv.w, acc.w);
    }
    int r = row0 + row;
    if (r < n) *(float4*)(C + (size_t)r * OUTF + c4) = acc;
}

// ---------------- aggregation 16 wide + bias + log_softmax (+ deg re-zero) ----------------
__global__ __launch_bounds__(256) void k_agg16(const float* __restrict__ h,
                                               const float* __restrict__ b3,
                                               float* __restrict__ out, int n) {
    int gi   = blockIdx.x * blockDim.x + threadIdx.x;
    int node = gi >> 2;
    int q    = gi & 3;
    if (node >= n) return;
    if (q == 0) g_deg[node] = 0;  // restore invariant for next call
    int beg = g_rowptr[node];
    int end = g_rowptr[node + 1];
    float dn = g_dinv[node];
    int c4 = q * 4;

    float4 acc = *(const float4*)(h + (size_t)node * OUTF + c4);
    float w0 = dn * dn;
    acc.x *= w0; acc.y *= w0; acc.z *= w0; acc.w *= w0;

#pragma unroll 4
    for (int e = beg; e < end; e++) {
        int2 p  = __ldg(&g_csr_sn[e]);
        int   s = p.x;
        float w = __low2float(bits2h2((unsigned)p.y));
        float4 hv = __ldg((const float4*)(h + (size_t)s * OUTF + c4));
        acc.x = fmaf(w, hv.x, acc.x);
        acc.y = fmaf(w, hv.y, acc.y);
        acc.z = fmaf(w, hv.z, acc.z);
        acc.w = fmaf(w, hv.w, acc.w);
    }

    float4 bv = *(const float4*)(b3 + c4);
    float z0 = acc.x + bv.x, z1 = acc.y + bv.y, z2 = acc.z + bv.z, z3 = acc.w + bv.w;

    float mx = fmaxf(fmaxf(z0, z1), fmaxf(z2, z3));
    mx = fmaxf(mx, __shfl_xor_sync(0xffffffffu, mx, 1));
    mx = fmaxf(mx, __shfl_xor_sync(0xffffffffu, mx, 2));

    float se = expf(z0 - mx) + expf(z1 - mx) + expf(z2 - mx) + expf(z3 - mx);
    se += __shfl_xor_sync(0xffffffffu, se, 1);
    se += __shfl_xor_sync(0xffffffffu, se, 2);
    float l = logf(se);

    float4 o;
    o.x = z0 - mx - l; o.y = z1 - mx - l; o.z = z2 - mx - l; o.w = z3 - mx - l;
    *(float4*)(out + (size_t)node * OUTF + c4) = o;
}

// ---------------- launch ----------------
extern "C" void kernel_launch(void* const* d_in, const int* in_sizes, int n_in,
                              void* d_out, int out_size) {
    const float* x   = (const float*)d_in[0];
    const int*   ei  = (const int*)d_in[1];   // int32 (JAX x64-disabled)
    const float* W1  = (const float*)d_in[2];
    const float* b1  = (const float*)d_in[3];
    const float* g1  = (const float*)d_in[4];
    const float* be1 = (const float*)d_in[5];
    const float* m1  = (const float*)d_in[6];
    const float* v1  = (const float*)d_in[7];
    const float* W2  = (const float*)d_in[8];
    const float* b2  = (const float*)d_in[9];
    const float* g2  = (const float*)d_in[10];
    const float* be2 = (const float*)d_in[11];
    const float* m2  = (const float*)d_in[12];
    const float* v2  = (const float*)d_in[13];
    const float* W3  = (const float*)d_in[14];
    const float* b3  = (const float*)d_in[15];
    float*       out = (float*)d_out;

    void *phh = nullptr, *px2h = nullptr, *ph16 = nullptr, *pw1 = nullptr, *pw2 = nullptr;
    cudaGetSymbolAddress(&phh,  g_hh);
    cudaGetSymbolAddress(&px2h, g_x2h);
    cudaGetSymbolAddress(&ph16, g_h16);
    cudaGetSymbolAddress(&pw1,  g_w1p);
    cudaGetSymbolAddress(&pw2,  g_w2p);
    __half*   hh_buf  = (__half*)phh;
    __half*   x2h_buf = (__half*)px2h;
    float*    h16_buf = (float*)ph16;
    unsigned* w1p     = (unsigned*)pw1;
    unsigned* w2p     = (unsigned*)pw2;

    int n = in_sizes[0] / FEAT;
    int e = in_sizes[1] / 2;

    int nb     = (n + 1023) / 1024;
    int gblk   = (n + 63) / 64;
    int gA     = gblk / 2;
    int gB     = gblk - gA;
    int ablk   = ((n * 32) + 255) / 256;   // warp per node
    int a16blk = ((n * 4) + 255) / 256;

    // L0: BN prep + W fragment permute + degree count
    k_prepw<<<65 + EBLK, 256>>>(W1, W2, b1, g1, be1, m1, v1,
                                b2, g2, be2, m2, v2, ei, e, n);
    // L1: gemm L1 rows A  ||  scan (rowptr/cursor/dinv)
    k_gemm_scan<<<gA + nb, 256>>>(x, w1p, hh_buf, n, gA, nb);
    // L2: gemm L1 rows B  ||  grid-stride CSR fill
    k_gemm_fill<<<gB + EBLK, 256>>>(x, 0, w1p, hh_buf, n, gA, gB, ei, e);

    k_agg128<<<ablk, 256>>>(hh_buf, x2h_buf, 0, n);
    // layer 2 (pure gemm, fp16 input)
    k_gemm_fill<<<gblk, 256>>>(x2h_buf, 1, w2p, hh_buf, n, 0, gblk, ei, 0);
    k_agg128<<<ablk, 256>>>(hh_buf, x2h_buf, FEAT, n);
    // layer 3
    k_gemm16<<<gblk, 256>>>(x2h_buf, W3, h16_buf, n);
    k_agg16<<<a16blk, 256>>>(h16_buf, b3, out, n);
}

// round 17
// speedup vs baseline: 1.0386x; 1.0386x over previous
#include <cuda_runtime.h>
#include <cuda_fp16.h>
#include <math.h>
#include <stdint.h>

#define FEAT 128
#define OUTF 16
#define NMAX 50000
#define EMAX 800000
#define BN_EPS 1e-5f
#define EBLK 256            // grid-stride worker blocks
#define XPAD 136            // smem row pitch in halves (conflict-free frag loads)

typedef unsigned long long u64;

// ---------------- scratch (no allocations allowed) ----------------
__device__ __half g_xin[(size_t)NMAX * FEAT];  // fp16 copy of input x
__device__ __half g_hh[(size_t)NMAX * FEAT];   // fp16 GEMM output (layers 1-2)
__device__ __half g_x2h[(size_t)NMAX * FEAT];  // fp16 post-aggregation activation
__device__ float  g_h16[(size_t)NMAX * OUTF];  // fp32 GEMM output (layer 3)
__device__ unsigned g_w1p[8192];               // W1 fragment-permuted fp16x2
__device__ unsigned g_w2p[8192];               // W2 fragment-permuted fp16x2
__device__ int    g_deg[NMAX];                 // zero at module load; re-zeroed by agg16
__device__ int    g_rowptr[NMAX + 1];
__device__ int    g_cursor[NMAX];
__device__ float  g_dinv[NMAX];
__device__ int2   g_csr_sn[EMAX];              // packed (src, norm as dup half2)
__device__ float  g_S[2 * FEAT];
__device__ float  g_T[2 * FEAT];

// ---------------- helpers ----------------
__device__ __forceinline__ unsigned h2bits(__half2 h) {
    return *reinterpret_cast<unsigned*>(&h);
}
__device__ __forceinline__ __half2 bits2h2(unsigned u) {
    return *reinterpret_cast<__half2*>(&u);
}
__device__ __forceinline__ void mma16816(float c[4], const unsigned a[4], const unsigned b[2]) {
    asm volatile(
        "mma.sync.aligned.m16n8k16.row.col.f32.f16.f16.f32 "
        "{%0,%1,%2,%3}, {%4,%5,%6,%7}, {%8,%9}, {%0,%1,%2,%3};"
        : "+f"(c[0]), "+f"(c[1]), "+f"(c[2]), "+f"(c[3])
        : "r"(a[0]), "r"(a[1]), "r"(a[2]), "r"(a[3]), "r"(b[0]), "r"(b[1]));
}
__device__ __forceinline__ void ldsm_x4(unsigned r[4], const __half* p) {
    unsigned addr = (unsigned)__cvta_generic_to_shared(p);
    asm volatile("ldmatrix.sync.aligned.m8n8.x4.shared.b16 {%0,%1,%2,%3}, [%4];"
                 : "=r"(r[0]), "=r"(r[1]), "=r"(r[2]), "=r"(r[3]) : "r"(addr));
}

// ---------------- HMMA GEMM block: X tile in smem (LDSM frags), W fragment-permuted global ----------------
// Per warp per kstep: 2 LDSM.x4 (A) + 8 coalesced LDG.32 (B) + 8 HMMA.
__device__ __forceinline__ void gemm128_block(const __half* __restrict__ Xh,
                                              const unsigned* __restrict__ Wp,
                                              __half* __restrict__ C,
                                              int n, int row0) {
    __shared__ __align__(16) __half xs[64 * XPAD];
    int t = threadIdx.x;

    // stage X tile (coalesced uint2 loads; rows >= n zero-filled)
    {
        int r  = t >> 2;
        int cg = t & 3;
        int grow = row0 + r;
        bool ok = grow < n;
        const uint2* src = (const uint2*)(Xh + (size_t)grow * FEAT + cg * 32);
#pragma unroll
        for (int u = 0; u < 8; u++) {
            uint2 v = ok ? __ldg(src + u) : make_uint2(0u, 0u);
            *(uint2*)(xs + r * XPAD + cg * 32 + u * 4) = v;
        }
    }
    __syncthreads();

    int lane = t & 31, w = t >> 5;
    int wm = w >> 2, wn = w & 3;          // m-half (32 rows), n-quarter (32 cols)
    int grp = lane >> 2, qid = lane & 3;

    // ldmatrix row/col addressing: lane&15 -> row within 16, lane>>4 -> col half
    int lrow = lane & 15;
    int lcol = (lane >> 4) << 3;

    float acc[2][4][4];
#pragma unroll
    for (int mt = 0; mt < 2; mt++)
#pragma unroll
        for (int nt = 0; nt < 4; nt++)
#pragma unroll
            for (int f = 0; f < 4; f++) acc[mt][nt][f] = 0.f;

#pragma unroll
    for (int ks = 0; ks < 8; ks++) {
        int k0 = ks * 16;
        unsigned a[2][4];
#pragma unroll
        for (int mt = 0; mt < 2; mt++) {
            const __half* p = xs + (wm * 32 + mt * 16 + lrow) * XPAD + k0 + lcol;
            ldsm_x4(a[mt], p);
        }
        unsigned b[4][2];
#pragma unroll
        for (int nt = 0; nt < 4; nt++) {
            const unsigned* wp = Wp + ((((wn * 4 + nt) * 8 + ks) * 2) * 32) + lane;
            b[nt][0] = __ldg(wp);
            b[nt][1] = __ldg(wp + 32);
        }
#pragma unroll
        for (int nt = 0; nt < 4; nt++) {
            mma16816(acc[0][nt], a[0], b[nt]);
            mma16816(acc[1][nt], a[1], b[nt]);
        }
    }

#pragma unroll
    for (int mt = 0; mt < 2; mt++) {
        int r0 = row0 + wm * 32 + mt * 16 + grp;
        int r1 = r0 + 8;
#pragma unroll
        for (int nt = 0; nt < 4; nt++) {
            int cc = wn * 32 + nt * 8 + qid * 2;
            if (r0 < n)
                *(unsigned*)(C + (size_t)r0 * FEAT + cc) =
                    h2bits(__floats2half2_rn(acc[mt][nt][0], acc[mt][nt][1]));
            if (r1 < n)
                *(unsigned*)(C + (size_t)r1 * FEAT + cc) =
                    h2bits(__floats2half2_rn(acc[mt][nt][2], acc[mt][nt][3]));
        }
    }
}

// ---------------- prep: BN affine + W fragment permute + x fp16 + degree count ----------------
// W frag layout: idx = (((wn*4+nt)*8+ks)*2+reg)*32+lane ; value = half2(W[k][n], W[k+1][n])
// with n = wn*32+nt*8+(lane>>2), k = ks*16+(lane&3)*2+reg*8.
__global__ void k_prepw(const float* __restrict__ x,
                        const float* __restrict__ W1, const float* __restrict__ W2,
                        const float* __restrict__ b1, const float* __restrict__ g1,
                        const float* __restrict__ be1, const float* __restrict__ m1,
                        const float* __restrict__ v1,
                        const float* __restrict__ b2, const float* __restrict__ g2,
                        const float* __restrict__ be2, const float* __restrict__ m2,
                        const float* __restrict__ v2,
                        const int* __restrict__ ei, int e, int n) {
    int b = blockIdx.x;
    int t = threadIdx.x;
    if (b == 0) {
        if (t < FEAT) {
            float s = rsqrtf(v1[t] + BN_EPS) * g1[t];
            g_S[t] = s;
            g_T[t] = (b1[t] - m1[t]) * s + be1[t];
        } else {
            int c = t - FEAT;
            float s = rsqrtf(v2[c] + BN_EPS) * g2[c];
            g_S[FEAT + c] = s;
            g_T[FEAT + c] = (b2[c] - m2[c]) * s + be2[c];
        }
        return;
    }
    if (b <= 64) {
        const float* W = (b <= 32) ? W1 : W2;
        unsigned* Wp   = (b <= 32) ? g_w1p : g_w2p;
        int idx = ((b <= 32) ? (b - 1) : (b - 33)) * 256 + t;   // 0..8191
        int lane = idx & 31;
        int reg  = (idx >> 5) & 1;
        int ks   = (idx >> 6) & 7;
        int nt   = (idx >> 9) & 3;
        int wn   = (idx >> 11) & 3;
        int nn = wn * 32 + nt * 8 + (lane >> 2);
        int k  = ks * 16 + (lane & 3) * 2 + reg * 8;
        __half2 v = __floats2half2_rn(W[k * FEAT + nn], W[(k + 1) * FEAT + nn]);
        Wp[idx] = h2bits(v);
        return;
    }
    int wb = b - 65;
    for (int i = wb * 256 + t; i < e; i += EBLK * 256) {
        int d = ei[e + i];
        d = min(max(d, 0), n - 1);
        atomicAdd(&g_deg[d], 1);
    }
    int nchunk = n * (FEAT / 4);
    for (int i = wb * 256 + t; i < nchunk; i += EBLK * 256) {
        float4 v = __ldg((const float4*)x + i);
        uint2 p = make_uint2(h2bits(__floats2half2_rn(v.x, v.y)),
                             h2bits(__floats2half2_rn(v.z, v.w)));
        *((uint2*)g_xin + i) = p;
    }
}

// ---------------- single-kernel scan: rowptr/cursor/dinv from deg ----------------
__global__ void k_scan(int n, int nb) {
    __shared__ int sm[1024];
    __shared__ int wred[32];
    int t   = threadIdx.x;
    int bid = blockIdx.x;
    int i   = bid * 1024 + t;
    int v = (i < n) ? g_deg[i] : 0;
    if (i < n) g_dinv[i] = rsqrtf((float)(v + 1));  // +1 self loop
    sm[t] = v;

    int base = bid * 1024;
    int part = 0;
    for (int j = t; j < base; j += 1024) part += g_deg[j];
#pragma unroll
    for (int o = 16; o > 0; o >>= 1) part += __shfl_xor_sync(0xffffffffu, part, o);
    if ((t & 31) == 0) wred[t >> 5] = part;
    __syncthreads();
    if (t < 32) {
        int s = wred[t];
#pragma unroll
        for (int o = 16; o > 0; o >>= 1) s += __shfl_xor_sync(0xffffffffu, s, o);
        if (t == 0) wred[0] = s;
    }
    __syncthreads();
    int pref = wred[0];

    for (int off = 1; off < 1024; off <<= 1) {
        int u = 0;
        if (t >= off) u = sm[t - off];
        __syncthreads();
        sm[t] += u;
        __syncthreads();
    }
    if (i < n) {
        int excl = pref + sm[t] - v;
        g_rowptr[i] = excl;
        g_cursor[i] = excl;
    }
    if (bid == nb - 1 && t == 1023) g_rowptr[n] = pref + sm[1023];
}

// ---------------- GEMM launch: blocks [0,gblk) gemm; rest grid-stride CSR fill ----------------
__global__ __launch_bounds__(256)
void k_gemm_fill(const __half* __restrict__ Xh,
                 const unsigned* __restrict__ Wp, __half* __restrict__ C,
                 int n, int gblk, const int* __restrict__ ei, int e) {
    if ((int)blockIdx.x < gblk) {
        gemm128_block(Xh, Wp, C, n, blockIdx.x * 64);
        return;
    }
    for (int i = ((int)blockIdx.x - gblk) * 256 + threadIdx.x; i < e; i += EBLK * 256) {
        int s = ei[i];
        int d = ei[e + i];
        s = min(max(s, 0), n - 1);
        d = min(max(d, 0), n - 1);
        int p = atomicAdd(&g_cursor[d], 1);
        float w = g_dinv[s] * g_dinv[d];
        g_csr_sn[p] = make_int2(s, (int)h2bits(__floats2half2_rn(w, w)));
    }
}

// ---------------- pull aggregation (R12-proven): warp/node, half2 accum ----------------
__global__ __launch_bounds__(256) void k_agg128(const __half* __restrict__ hh,
                                                __half* __restrict__ outh,
                                                int soff, int n) {
    int gw   = (blockIdx.x * blockDim.x + threadIdx.x) >> 5;
    int lane = threadIdx.x & 31;
    if (gw >= n) return;
    int node = gw;
    int beg = g_rowptr[node];
    int end = g_rowptr[node + 1];
    float dn = g_dinv[node];
    int c4 = lane * 4;

    __half2 hacc0 = __float2half2_rn(0.f);
    __half2 hacc1 = __float2half2_rn(0.f);

#pragma unroll 4
    for (int e = beg; e < end; e++) {
        int2 p  = __ldg(&g_csr_sn[e]);
        __half2 nh = bits2h2((unsigned)p.y);
        uint2 raw = __ldg((const uint2*)(hh + (size_t)p.x * FEAT + c4));
        hacc0 = __hfma2(nh, bits2h2(raw.x), hacc0);
        hacc1 = __hfma2(nh, bits2h2(raw.y), hacc1);
    }

    float4 acc;
    {
        uint2 raw = __ldg((const uint2*)(hh + (size_t)node * FEAT + c4));
        float2 a = __half22float2(bits2h2(raw.x));
        float2 b = __half22float2(bits2h2(raw.y));
        float w0 = dn * dn;
        float2 e0 = __half22float2(hacc0);
        float2 e1 = __half22float2(hacc1);
        acc.x = fmaf(a.x, w0, e0.x);
        acc.y = fmaf(a.y, w0, e0.y);
        acc.z = fmaf(b.x, w0, e1.x);
        acc.w = fmaf(b.y, w0, e1.y);
    }

    float4 sv = *(const float4*)(g_S + soff + c4);
    float4 tv = *(const float4*)(g_T + soff + c4);
    float ox = fmaxf(fmaf(acc.x, sv.x, tv.x), 0.f);
    float oy = fmaxf(fmaf(acc.y, sv.y, tv.y), 0.f);
    float oz = fmaxf(fmaf(acc.z, sv.z, tv.z), 0.f);
    float ow = fmaxf(fmaf(acc.w, sv.w, tv.w), 0.f);
    uint2 o = make_uint2(h2bits(__floats2half2_rn(ox, oy)),
                         h2bits(__floats2half2_rn(oz, ow)));
    *(uint2*)(outh + (size_t)node * FEAT + c4) = o;
}

// ---------------- GEMM: C[n,16] = X[n,128](fp16) @ W3[128,16] (fp32 math) ----------------
__global__ __launch_bounds__(256) void k_gemm16(const __half* __restrict__ Xh,
                                                const float* __restrict__ W,
                                                float* __restrict__ C, int n) {
    __shared__ float xs[64 * 132];
    int t = threadIdx.x;
    int row0 = blockIdx.x * 64;

    for (int i = t; i < 64 * 32; i += 256) {
        int r  = i >> 5;
        int c4 = (i & 31) * 4;
        float4 v = make_float4(0.f, 0.f, 0.f, 0.f);
        if (row0 + r < n) {
            uint2 raw = __ldg((const uint2*)(Xh + (size_t)(row0 + r) * FEAT + c4));
            float2 a = __half22float2(bits2h2(raw.x));
            float2 b = __half22float2(bits2h2(raw.y));
            v = make_float4(a.x, a.y, b.x, b.y);
        }
        *(float4*)(xs + r * 132 + c4) = v;
    }
    __syncthreads();

    int c4  = (t & 3) * 4;
    int row = t >> 2;
    float4 acc = make_float4(0.f, 0.f, 0.f, 0.f);
    const float* xr = xs + row * 132;
#pragma unroll 4
    for (int k = 0; k < FEAT; k++) {
        float4 wv = __ldg((const float4*)(W + k * OUTF + c4));
        float xv  = xr[k];
        acc.x = fmaf(xv, wv.x, acc.x);
        acc.y = fmaf(xv, wv.y, acc.y);
        acc.z = fmaf(xv, wv.z, acc.z);
        acc.w = fmaf(xv, wv.w, acc.w);
    }
    int r = row0 + row;
    if (r < n) *(float4*)(C + (size_t)r * OUTF + c4) = acc;
}

// ---------------- aggregation 16 wide + bias + log_softmax (+ deg re-zero) ----------------
__global__ __launch_bounds__(256) void k_agg16(const float* __restrict__ h,
                                               const float* __restrict__ b3,
                                               float* __restrict__ out, int n) {
    int gi   = blockIdx.x * blockDim.x + threadIdx.x;
    int node = gi >> 2;
    int q    = gi & 3;
    if (node >= n) return;
    if (q == 0) g_deg[node] = 0;  // restore invariant for next call
    int beg = g_rowptr[node];
    int end = g_rowptr[node + 1];
    float dn = g_dinv[node];
    int c4 = q * 4;

    float4 acc = *(const float4*)(h + (size_t)node * OUTF + c4);
    float w0 = dn * dn;
    acc.x *= w0; acc.y *= w0; acc.z *= w0; acc.w *= w0;

#pragma unroll 4
    for (int e = beg; e < end; e++) {
        int2 p  = __ldg(&g_csr_sn[e]);
        int   s = p.x;
        float w = __low2float(bits2h2((unsigned)p.y));
        float4 hv = __ldg((const float4*)(h + (size_t)s * OUTF + c4));
        acc.x = fmaf(w, hv.x, acc.x);
        acc.y = fmaf(w, hv.y, acc.y);
        acc.z = fmaf(w, hv.z, acc.z);
        acc.w = fmaf(w, hv.w, acc.w);
    }

    float4 bv = *(const float4*)(b3 + c4);
    float z0 = acc.x + bv.x, z1 = acc.y + bv.y, z2 = acc.z + bv.z, z3 = acc.w + bv.w;

    float mx = fmaxf(fmaxf(z0, z1), fmaxf(z2, z3));
    mx = fmaxf(mx, __shfl_xor_sync(0xffffffffu, mx, 1));
    mx = fmaxf(mx, __shfl_xor_sync(0xffffffffu, mx, 2));

    float se = expf(z0 - mx) + expf(z1 - mx) + expf(z2 - mx) + expf(z3 - mx);
    se += __shfl_xor_sync(0xffffffffu, se, 1);
    se += __shfl_xor_sync(0xffffffffu, se, 2);
    float l = logf(se);

    float4 o;
    o.x = z0 - mx - l; o.y = z1 - mx - l; o.z = z2 - mx - l; o.w = z3 - mx - l;
    *(float4*)(out + (size_t)node * OUTF + c4) = o;
}

// ---------------- launch ----------------
extern "C" void kernel_launch(void* const* d_in, const int* in_sizes, int n_in,
                              void* d_out, int out_size) {
    const float* x   = (const float*)d_in[0];
    const int*   ei  = (const int*)d_in[1];   // int32 (JAX x64-disabled)
    const float* W1  = (const float*)d_in[2];
    const float* b1  = (const float*)d_in[3];
    const float* g1  = (const float*)d_in[4];
    const float* be1 = (const float*)d_in[5];
    const float* m1  = (const float*)d_in[6];
    const float* v1  = (const float*)d_in[7];
    const float* W2  = (const float*)d_in[8];
    const float* b2  = (const float*)d_in[9];
    const float* g2  = (const float*)d_in[10];
    const float* be2 = (const float*)d_in[11];
    const float* m2  = (const float*)d_in[12];
    const float* v2  = (const float*)d_in[13];
    const float* W3  = (const float*)d_in[14];
    const float* b3  = (const float*)d_in[15];
    float*       out = (float*)d_out;

    void *pxin = nullptr, *phh = nullptr, *px2h = nullptr, *ph16 = nullptr,
         *pw1 = nullptr, *pw2 = nullptr;
    cudaGetSymbolAddress(&pxin, g_xin);
    cudaGetSymbolAddress(&phh,  g_hh);
    cudaGetSymbolAddress(&px2h, g_x2h);
    cudaGetSymbolAddress(&ph16, g_h16);
    cudaGetSymbolAddress(&pw1,  g_w1p);
    cudaGetSymbolAddress(&pw2,  g_w2p);
    __half*   xin_buf = (__half*)pxin;
    __half*   hh_buf  = (__half*)phh;
    __half*   x2h_buf = (__half*)px2h;
    float*    h16_buf = (float*)ph16;
    unsigned* w1p     = (unsigned*)pw1;
    unsigned* w2p     = (unsigned*)pw2;

    int n = in_sizes[0] / FEAT;
    int e = in_sizes[1] / 2;

    int nb     = (n + 1023) / 1024;
    int gblk   = (n + 63) / 64;
    int ablk   = ((n * 32) + 255) / 256;   // warp per node
    int a16blk = ((n * 4) + 255) / 256;

    // L0: BN prep + W fragment permute + x fp16 convert + degree count
    k_prepw<<<65 + EBLK, 256>>>(x, W1, W2, b1, g1, be1, m1, v1,
                                b2, g2, be2, m2, v2, ei, e, n);
    // L1: scan (rowptr/cursor/dinv)
    k_scan<<<nb, 1024>>>(n, nb);
    // L2: gemm layer 1 + grid-stride CSR fill overlapped
    k_gemm_fill<<<gblk + EBLK, 256>>>(xin_buf, w1p, hh_buf, n, gblk, ei, e);

    k_agg128<<<ablk, 256>>>(hh_buf, x2h_buf, 0, n);
    // layer 2 (pure gemm)
    k_gemm_fill<<<gblk, 256>>>(x2h_buf, w2p, hh_buf, n, gblk, ei, 0);
    k_agg128<<<ablk, 256>>>(hh_buf, x2h_buf, FEAT, n);
    // layer 3
    k_gemm16<<<gblk, 256>>>(x2h_buf, W3, h16_buf, n);
    k_agg16<<<a16blk, 256>>>(h16_buf, b3, out, n);
}